// round 8
// baseline (speedup 1.0000x reference)
#include <cuda_runtime.h>

// LatticeSnake: B=16, N=48, K=7, PAD=3. Reference scatters 48 acids + 47
// inters into a 195^3 lattice (in-order, last-write-wins), extracts a 7^3
// window at each acid's idx2, masks by mask[n].
//
// R8: scatter design as R7 (all-pairs candidate x window; 32-bit atomicMax
// over candidate index == last-write-wins ordering), with the output store
// moved OFF the critical path: the CTA zeroes its whole contiguous output
// block with float4 stores at cycle ~0 (no input dependency), and after the
// scatter only the ~1-5 nonzero cells per CTA are overwritten. __syncthreads
// orders zero-stores before overwrite-stores within the CTA.
//
// Kernel is launch-latency bound (all pipes <5% since R3); dur_us has sat in
// the 6.4-6.7us replay-floor band for 4 rounds.
//
// mask is int32 (harness materializes JAX bool as 4-byte ints).

#define NACID   48
#define KWIN    7
#define PADW    3
#define CELLS   (KWIN * KWIN * KWIN)   // 343
#define NCAND   (2 * NACID - 1)        // 95
#define WPC     4                      // windows per CTA
#define SLICES  (NACID / WPC)          // 12
#define NTHREADS 256

__global__ __launch_bounds__(NTHREADS)
void lattice_snake_kernel(const float* __restrict__ acids,
                          const int* __restrict__ mask,
                          const int* __restrict__ idx,
                          float* __restrict__ out)
{
    __shared__ __align__(16) int buf[WPC * CELLS];  // winner cand index + 1 (0 = empty)
    __shared__ int4  cand[NCAND];                   // cx, cy, cz, value bits
    __shared__ int   wbase[WPC][3];
    __shared__ float wmask[WPC];

    const int slice = blockIdx.x;      // 0..11
    const int b     = blockIdx.y;      // 0..15
    const int t     = threadIdx.x;

    float* outb = out + (b * NACID + slice * WPC) * CELLS;  // 1372 floats, 16B-aligned

    // ---- stage 0: zero output block immediately (independent of all loads) ----
    {
        float4* oz = (float4*)outb;
        #pragma unroll
        for (int c = t; c < (WPC * CELLS) / 4; c += NTHREADS)   // 343 float4s
            oz[c] = make_float4(0.f, 0.f, 0.f, 0.f);
    }

    // ---- stage 1: zero hit buffer, build candidates, window bases ----
    {
        int4* bz = (int4*)buf;
        #pragma unroll
        for (int c = t; c < (WPC * CELLS) / 4; c += NTHREADS)
            bz[c] = make_int4(0, 0, 0, 0);
    }

    if (t < NCAND) {
        int cx, cy, cz, live;
        float v;
        if (t < NACID) {
            cx = 2 * idx[b * NACID * 3 + 3 * t + 0] + 94 + PADW;
            cy = 2 * idx[b * NACID * 3 + 3 * t + 1] + 94 + PADW;
            cz = 2 * idx[b * NACID * 3 + 3 * t + 2] + 94 + PADW;
            live = mask[b * NACID + t];
            v = acids[b * NACID + t];
        } else {
            const int j = t - NACID;   // 0..46
            const int* ij = idx + b * NACID * 3 + 3 * j;
            cx = ij[0] + ij[3] + 94 + PADW;
            cy = ij[1] + ij[4] + 94 + PADW;
            cz = ij[2] + ij[5] + 94 + PADW;
            live = mask[b * NACID + j + 1];
            v = acids[b * NACID + j] + acids[b * NACID + j + 1] + 1.0f;
        }
        if (!live) cx = 1 << 20;       // out of unsigned<7 range -> never hits
        cand[t] = make_int4(cx, cy, cz, __float_as_int(v));
    } else if (t >= 128 && t < 128 + WPC) {
        const int w = t - 128;
        const int n = slice * WPC + w;
        wbase[w][0] = 2 * idx[b * NACID * 3 + 3 * n + 0] + 94;
        wbase[w][1] = 2 * idx[b * NACID * 3 + 3 * n + 1] + 94;
        wbase[w][2] = 2 * idx[b * NACID * 3 + 3 * n + 2] + 94;
        wmask[w] = mask[b * NACID + n] ? 1.0f : 0.0f;
    }
    __syncthreads();

    // ---- stage 2: all-pairs candidate x window scatter (380 pairs) ----
    #pragma unroll
    for (int p = t; p < WPC * NCAND; p += NTHREADS) {
        const int w = p / NCAND;
        const int i = p - w * NCAND;
        const int4 c = cand[i];
        const int dx = c.x - wbase[w][0];
        const int dy = c.y - wbase[w][1];
        const int dz = c.z - wbase[w][2];
        if ((unsigned)dx < KWIN && (unsigned)dy < KWIN && (unsigned)dz < KWIN)
            atomicMax(&buf[w * CELLS + dx * 49 + dy * 7 + dz], i + 1);
    }
    __syncthreads();

    // ---- stage 3: sparse overwrite of hit cells only ----
    {
        const int4* bs = (const int4*)buf;
        #pragma unroll
        for (int q = t; q < (WPC * CELLS) / 4; q += NTHREADS) {
            const int4 h = bs[q];
            if (h.x | h.y | h.z | h.w) {      // rare: ~1-5 hits per CTA total
                const int c = 4 * q;
                if (h.x) outb[c + 0] = __int_as_float(cand[h.x - 1].w) * wmask[(c + 0) / CELLS];
                if (h.y) outb[c + 1] = __int_as_float(cand[h.y - 1].w) * wmask[(c + 1) / CELLS];
                if (h.z) outb[c + 2] = __int_as_float(cand[h.z - 1].w) * wmask[(c + 2) / CELLS];
                if (h.w) outb[c + 3] = __int_as_float(cand[h.w - 1].w) * wmask[(c + 3) / CELLS];
            }
        }
    }
}

extern "C" void kernel_launch(void* const* d_in, const int* in_sizes, int n_in,
                              void* d_out, int out_size)
{
    const float* acids = (const float*)d_in[0];   // (B, N) float32
    const int*   mask  = (const int*)d_in[1];     // (B, N) bool -> int32
    const int*   idx   = (const int*)d_in[2];     // (B, N, 3) int32
    float*       out   = (float*)d_out;           // (B, N, 7,7,7, 1) float32

    dim3 grid(SLICES, 16);
    lattice_snake_kernel<<<grid, NTHREADS>>>(acids, mask, idx, out);
}

// round 10
// speedup vs baseline: 1.0337x; 1.0337x over previous
#include <cuda_runtime.h>

// LatticeSnake: B=16, N=48, K=7, PAD=3. Reference scatters 48 acids + 47
// inters into a 195^3 lattice (in-order, last-write-wins), extracts a 7^3
// window at each acid's idx2, masks by mask[n].
//
// R10 (R9 alignment fix): all-pairs candidate x window scatter. 32-bit
// atomicMax over candidate index (+1) == last-write-wins scatter order; value
// looked up from cand[] afterward. Output block zeroed at cycle ~0 with
// float2 stores (per-CTA block = 2058 floats = 8232 B: 8-byte aligned for
// every slice, NOT 16 — R9's float4 zero trapped on odd slices). Only the
// ~1-5 hit cells per CTA are overwritten after the barrier.
// Launch shape: WPC=6, 512 threads, grid 8x16 = 128 CTAs (single wave).
//
// Kernel is launch-latency bound: over R3-R8 all pipes sat <5%, and bench
// dur (6.40-6.88us) was uncorrelated with ncu kernel time (4.48-4.93us).
//
// mask is int32 (harness materializes JAX bool as 4-byte ints).

#define NACID   48
#define KWIN    7
#define PADW    3
#define CELLS   (KWIN * KWIN * KWIN)   // 343
#define NCAND   (2 * NACID - 1)        // 95
#define WPC     6                      // windows per CTA
#define SLICES  (NACID / WPC)          // 8
#define NTHREADS 512

__global__ __launch_bounds__(NTHREADS)
void lattice_snake_kernel(const float* __restrict__ acids,
                          const int* __restrict__ mask,
                          const int* __restrict__ idx,
                          float* __restrict__ out)
{
    __shared__ __align__(16) int buf[WPC * CELLS + 2]; // winner cand idx+1 (0=empty); +2 pad -> 2060 = 515 int4
    __shared__ int4  cand[NCAND];                      // cx, cy, cz, value bits
    __shared__ int   wbase[WPC][3];
    __shared__ float wmask[WPC];

    const int slice = blockIdx.x;      // 0..7
    const int b     = blockIdx.y;      // 0..15
    const int t     = threadIdx.x;

    float* outb = out + (b * NACID + slice * WPC) * CELLS;  // 2058 floats, 8B-aligned

    // ---- stage 0: zero output block immediately (no input dependency) ----
    {
        float2* oz = (float2*)outb;                          // 1029 float2
        #pragma unroll
        for (int c = t; c < (WPC * CELLS) / 2; c += NTHREADS)
            oz[c] = make_float2(0.f, 0.f);
    }

    // ---- stage 1: zero hit buffer, build candidates, window bases ----
    {
        int4* bz = (int4*)buf;
        #pragma unroll
        for (int c = t; c < (WPC * CELLS + 2) / 4; c += NTHREADS)  // 515 int4
            bz[c] = make_int4(0, 0, 0, 0);
    }

    if (t < NCAND) {
        int cx, cy, cz, live;
        float v;
        if (t < NACID) {
            cx = 2 * idx[b * NACID * 3 + 3 * t + 0] + 94 + PADW;
            cy = 2 * idx[b * NACID * 3 + 3 * t + 1] + 94 + PADW;
            cz = 2 * idx[b * NACID * 3 + 3 * t + 2] + 94 + PADW;
            live = mask[b * NACID + t];
            v = acids[b * NACID + t];
        } else {
            const int j = t - NACID;   // 0..46
            const int* ij = idx + b * NACID * 3 + 3 * j;
            cx = ij[0] + ij[3] + 94 + PADW;
            cy = ij[1] + ij[4] + 94 + PADW;
            cz = ij[2] + ij[5] + 94 + PADW;
            live = mask[b * NACID + j + 1];
            v = acids[b * NACID + j] + acids[b * NACID + j + 1] + 1.0f;
        }
        if (!live) cx = 1 << 20;       // out of unsigned<7 range -> never hits
        cand[t] = make_int4(cx, cy, cz, __float_as_int(v));
    } else if (t >= 128 && t < 128 + WPC) {
        const int w = t - 128;
        const int n = slice * WPC + w;
        wbase[w][0] = 2 * idx[b * NACID * 3 + 3 * n + 0] + 94;
        wbase[w][1] = 2 * idx[b * NACID * 3 + 3 * n + 1] + 94;
        wbase[w][2] = 2 * idx[b * NACID * 3 + 3 * n + 2] + 94;
        wmask[w] = mask[b * NACID + n] ? 1.0f : 0.0f;
    }
    __syncthreads();

    // ---- stage 2: all-pairs candidate x window scatter (570 pairs) ----
    #pragma unroll
    for (int p = t; p < WPC * NCAND; p += NTHREADS) {
        const int w = p / NCAND;
        const int i = p - w * NCAND;
        const int4 c = cand[i];
        const int dx = c.x - wbase[w][0];
        const int dy = c.y - wbase[w][1];
        const int dz = c.z - wbase[w][2];
        if ((unsigned)dx < KWIN && (unsigned)dy < KWIN && (unsigned)dz < KWIN)
            atomicMax(&buf[w * CELLS + dx * 49 + dy * 7 + dz], i + 1);
    }
    __syncthreads();

    // ---- stage 3: sparse overwrite of hit cells only ----
    {
        const int4* bs = (const int4*)buf;
        #pragma unroll
        for (int q = t; q < (WPC * CELLS + 2) / 4; q += NTHREADS) {
            const int4 h = bs[q];
            if (h.x | h.y | h.z | h.w) {      // rare: ~1-5 hits per CTA
                const int c = 4 * q;
                if (h.x)                      outb[c + 0] = __int_as_float(cand[h.x - 1].w) * wmask[(c + 0) / CELLS];
                if (h.y)                      outb[c + 1] = __int_as_float(cand[h.y - 1].w) * wmask[(c + 1) / CELLS];
                if (h.z && c + 2 < WPC*CELLS) outb[c + 2] = __int_as_float(cand[h.z - 1].w) * wmask[(c + 2) / CELLS];
                if (h.w && c + 3 < WPC*CELLS) outb[c + 3] = __int_as_float(cand[h.w - 1].w) * wmask[(c + 3) / CELLS];
            }
        }
    }
}

extern "C" void kernel_launch(void* const* d_in, const int* in_sizes, int n_in,
                              void* d_out, int out_size)
{
    const float* acids = (const float*)d_in[0];   // (B, N) float32
    const int*   mask  = (const int*)d_in[1];     // (B, N) bool -> int32
    const int*   idx   = (const int*)d_in[2];     // (B, N, 3) int32
    float*       out   = (float*)d_out;           // (B, N, 7,7,7, 1) float32

    dim3 grid(SLICES, 16);
    lattice_snake_kernel<<<grid, NTHREADS>>>(acids, mask, idx, out);
}

// round 11
// speedup vs baseline: 1.0386x; 1.0048x over previous
#include <cuda_runtime.h>

// LatticeSnake: B=16, N=48, K=7, PAD=3. Reference scatters 48 acids + 47
// inters into a 195^3 lattice (in-order, last-write-wins), extracts a 7^3
// window at each acid's idx2, masks by mask[n].
//
// R11 (final form): each candidate thread scatters ITS OWN candidate against
// all 6 of the CTA's windows with a 64-bit packed atomicMax
// ((cand_index+1)<<32 | value_bits) — max over index == last-write-wins
// scatter order, value rides along. This removes the cand[] smem array and
// one barrier: critical path is LDG -> ATOMS -> BAR -> LDS -> STG, with the
// buf/output zeroing and wbase build hidden under the LDG shadow before the
// single zero-ordering barrier. Output zeroed with float2 (8232 B per-CTA
// block is 8-byte aligned only); sparse overwrite of the ~1-5 hit cells.
// Launch: WPC=6, 512 threads, grid 8x16 = 128 CTAs, single wave.
//
// Kernel is launch-latency bound: R3-R10 pipes all <5%; bench dur
// (6.40-6.88us) uncorrelated with ncu kernel time (4.48-4.93us).
//
// mask is int32 (harness materializes JAX bool as 4-byte ints).

#define NACID   48
#define KWIN    7
#define PADW    3
#define CELLS   (KWIN * KWIN * KWIN)   // 343
#define NCAND   (2 * NACID - 1)        // 95
#define WPC     6                      // windows per CTA
#define SLICES  (NACID / WPC)          // 8
#define NTHREADS 512

__global__ __launch_bounds__(NTHREADS)
void lattice_snake_kernel(const float* __restrict__ acids,
                          const int* __restrict__ mask,
                          const int* __restrict__ idx,
                          float* __restrict__ out)
{
    __shared__ __align__(16) unsigned long long buf[WPC * CELLS]; // (i+1)<<32 | valbits
    __shared__ int   wbase[WPC][3];
    __shared__ float wmask[WPC];

    const int slice = blockIdx.x;      // 0..7
    const int b     = blockIdx.y;      // 0..15
    const int t     = threadIdx.x;

    float* outb = out + (b * NACID + slice * WPC) * CELLS;  // 2058 floats, 8B-aligned

    // ---- stage A (all under the LDG shadow): zero output, zero buf, wbase ----
    {
        float2* oz = (float2*)outb;                          // 1029 float2
        #pragma unroll
        for (int c = t; c < (WPC * CELLS) / 2; c += NTHREADS)
            oz[c] = make_float2(0.f, 0.f);

        ulonglong2* bz = (ulonglong2*)buf;                   // 1029 u64x2
        #pragma unroll
        for (int c = t; c < (WPC * CELLS) / 2; c += NTHREADS)
            bz[c] = make_ulonglong2(0ULL, 0ULL);
    }
    if (t >= 128 && t < 128 + WPC) {
        const int w = t - 128;
        const int n = slice * WPC + w;
        wbase[w][0] = 2 * idx[b * NACID * 3 + 3 * n + 0] + 94;
        wbase[w][1] = 2 * idx[b * NACID * 3 + 3 * n + 1] + 94;
        wbase[w][2] = 2 * idx[b * NACID * 3 + 3 * n + 2] + 94;
        wmask[w] = mask[b * NACID + n] ? 1.0f : 0.0f;
    }

    // candidate build starts its global loads BEFORE the barrier (no smem dep)
    int cx = 1 << 20, cy = 0, cz = 0;
    float v = 0.0f;
    if (t < NCAND) {
        int live;
        if (t < NACID) {
            cx = 2 * idx[b * NACID * 3 + 3 * t + 0] + 94 + PADW;
            cy = 2 * idx[b * NACID * 3 + 3 * t + 1] + 94 + PADW;
            cz = 2 * idx[b * NACID * 3 + 3 * t + 2] + 94 + PADW;
            live = mask[b * NACID + t];
            v = acids[b * NACID + t];
        } else {
            const int j = t - NACID;   // 0..46
            const int* ij = idx + b * NACID * 3 + 3 * j;
            cx = ij[0] + ij[3] + 94 + PADW;
            cy = ij[1] + ij[4] + 94 + PADW;
            cz = ij[2] + ij[5] + 94 + PADW;
            live = mask[b * NACID + j + 1];
            v = acids[b * NACID + j] + acids[b * NACID + j + 1] + 1.0f;
        }
        if (!live) cx = 1 << 20;       // out of unsigned<7 range -> never hits
    }
    __syncthreads();   // orders buf zeroing (and wbase) before the atomics below

    // ---- stage B: each candidate thread scatters against all 6 windows ----
    if (t < NCAND) {
        const unsigned long long pk =
            ((unsigned long long)(t + 1) << 32) | (unsigned)__float_as_int(v);
        #pragma unroll
        for (int w = 0; w < WPC; ++w) {
            const int dx = cx - wbase[w][0];
            const int dy = cy - wbase[w][1];
            const int dz = cz - wbase[w][2];
            if ((unsigned)dx < KWIN && (unsigned)dy < KWIN && (unsigned)dz < KWIN)
                atomicMax(&buf[w * CELLS + dx * 49 + dy * 7 + dz], pk);
        }
    }
    __syncthreads();

    // ---- stage C: sparse overwrite of hit cells only ----
    {
        const ulonglong2* bs = (const ulonglong2*)buf;
        #pragma unroll
        for (int q = t; q < (WPC * CELLS) / 2; q += NTHREADS) {
            const ulonglong2 h = bs[q];
            if (h.x | h.y) {                  // rare: ~1-5 hits per CTA
                const int c = 2 * q;
                if (h.x >> 32) outb[c + 0] = __int_as_float((int)(unsigned)h.x) * wmask[(c + 0) / CELLS];
                if (h.y >> 32) outb[c + 1] = __int_as_float((int)(unsigned)h.y) * wmask[(c + 1) / CELLS];
            }
        }
    }
}

extern "C" void kernel_launch(void* const* d_in, const int* in_sizes, int n_in,
                              void* d_out, int out_size)
{
    const float* acids = (const float*)d_in[0];   // (B, N) float32
    const int*   mask  = (const int*)d_in[1];     // (B, N) bool -> int32
    const int*   idx   = (const int*)d_in[2];     // (B, N, 3) int32
    float*       out   = (float*)d_out;           // (B, N, 7,7,7, 1) float32

    dim3 grid(SLICES, 16);
    lattice_snake_kernel<<<grid, NTHREADS>>>(acids, mask, idx, out);
}